// round 1
// baseline (speedup 1.0000x reference)
#include <cuda_runtime.h>
#include <cuda_bf16.h>

// Quanvolution (2x2, 4 qubits, RY encoding + RY params + CNOT ring, <Z_q>).
//
// Closed form: per output pixel (b,x,y) with patch a00,a01,a10,a11 and
// weights w0..w3:
//   Zq = cos(pi*a_q + w_q)
//   ch0 = Z1*Z2*Z3, ch1 = Z0*Z1, ch2 = Z0*Z1*Z2, ch3 = Z0*Z1*Z2*Z3
// Derivation: RY(w)RY(th)|0> = RY(th+w)|0> (product state), CNOT ring is
// GF(2)-linear so <Z_q> after the ring is a product of pre-ring per-qubit
// <Z> = cos(theta) factors:
//   bit0 = a1^a2^a3, bit1 = a0^a1, bit2 = a0^a1^a2, bit3 = a0^a1^a2^a3.

#define H_IN 224
#define W_IN 224
#define L_OUT 223          // H_IN - 2 + 1
#define TILE 32            // output tile (TILE x TILE) per block
#define HALO (TILE + 1)    // input tile = 33 x 33

__device__ float g_cw[4];
__device__ float g_sw[4];

__global__ void quanv_setup_kernel(const float* __restrict__ w) {
    int q = threadIdx.x;
    if (q < 4) {
        g_cw[q] = cosf(w[q]);
        g_sw[q] = sinf(w[q]);
    }
}

__global__ __launch_bounds__(256) void quanv_main_kernel(
    const float* __restrict__ in,   // (64,1,224,224)
    float* __restrict__ out)        // (64,4,223,223)
{
    __shared__ float Cs[HALO][HALO + 3];   // pad to 36 -> conflict-free
    __shared__ float Ss[HALO][HALO + 3];

    const int b  = blockIdx.z;
    const int x0 = blockIdx.y * TILE;
    const int y0 = blockIdx.x * TILE;
    const int tid = threadIdx.x;

    const float* inb = in + (size_t)b * (H_IN * W_IN);

    // Load 33x33 halo tile, convert each element to (cos(pi*a), sin(pi*a)).
    #pragma unroll
    for (int i = tid; i < HALO * HALO; i += 256) {
        int r = i / HALO;
        int c = i - r * HALO;
        int gx = x0 + r;
        int gy = y0 + c;
        float v = 0.0f;
        if (gx < H_IN && gy < W_IN) v = __ldg(&inb[gx * W_IN + gy]);
        float s, cc;
        sincospif(v, &s, &cc);
        Cs[r][c] = cc;
        Ss[r][c] = s;
    }
    __syncthreads();

    const float cw0 = g_cw[0], sw0 = g_sw[0];
    const float cw1 = g_cw[1], sw1 = g_sw[1];
    const float cw2 = g_cw[2], sw2 = g_sw[2];
    const float cw3 = g_cw[3], sw3 = g_sw[3];

    const int ty = tid & 31;        // y within tile (warp-contiguous -> coalesced)
    const int tx0 = tid >> 5;       // 0..7, row group
    const int y = y0 + ty;
    if (y >= L_OUT) return;

    const size_t plane = (size_t)L_OUT * L_OUT;
    float* ob = out + (size_t)b * 4 * plane;

    #pragma unroll
    for (int k = 0; k < 4; k++) {
        const int rx = tx0 + k * 8;     // row within tile
        const int x = x0 + rx;
        if (x >= L_OUT) continue;

        // Zq = cos(pi*a_q)*cos(w_q) - sin(pi*a_q)*sin(w_q)
        const float Z0 = Cs[rx    ][ty    ] * cw0 - Ss[rx    ][ty    ] * sw0;
        const float Z1 = Cs[rx    ][ty + 1] * cw1 - Ss[rx    ][ty + 1] * sw1;
        const float Z2 = Cs[rx + 1][ty    ] * cw2 - Ss[rx + 1][ty    ] * sw2;
        const float Z3 = Cs[rx + 1][ty + 1] * cw3 - Ss[rx + 1][ty + 1] * sw3;

        const float p01  = Z0 * Z1;
        const float p12  = Z1 * Z2;
        const float p012 = p01 * Z2;

        float* o = ob + (size_t)x * L_OUT + y;
        o[0]         = p12 * Z3;     // ch0 = Z1 Z2 Z3
        o[plane]     = p01;          // ch1 = Z0 Z1
        o[2 * plane] = p012;         // ch2 = Z0 Z1 Z2
        o[3 * plane] = p012 * Z3;    // ch3 = Z0 Z1 Z2 Z3
    }
}

extern "C" void kernel_launch(void* const* d_in, const int* in_sizes, int n_in,
                              void* d_out, int out_size) {
    const float* inputs = (const float*)d_in[0];   // (64,1,224,224) float32
    const float* weight = (const float*)d_in[1];   // (1,4) float32
    float* out = (float*)d_out;                    // (64,4,223,223) float32

    quanv_setup_kernel<<<1, 32>>>(weight);

    dim3 grid((L_OUT + TILE - 1) / TILE,   // 7 (y tiles)
              (L_OUT + TILE - 1) / TILE,   // 7 (x tiles)
              64);                          // batch
    quanv_main_kernel<<<grid, 256>>>(inputs, out);
}